// round 14
// baseline (speedup 1.0000x reference)
#include <cuda_runtime.h>
#include <math.h>

#define NCOEF 21
#define OUT_PER_ATOM 1744          // 144 s + 64 radial + 1536 angular
#define EXP_VEC4 52                // (144+64)/4
#define WARPS_PER_CTA 8
#define STEP_S (8.0f / 15.0f)
#define STEP_R (4.0f / 15.0f)
#define STEP_A (4.0f / 15.0f)

__global__ __launch_bounds__(256, 5) void aev_kernel(const float* __restrict__ coeff,
                                                     float* __restrict__ out)
{
    // Per-warp private smem (only __syncwarp needed)
    __shared__ float4 s_fd[WARPS_PER_CTA][24];   // f_dist  [pair*4 + j4]
    __shared__ float  s_sn[WARPS_PER_CTA][16];   // [0..8]=s_coeffs, [9..12]=norms

    const int lane = threadIdx.x & 31;
    const int wid  = threadIdx.x >> 5;
    const int atom = blockIdx.x * WARPS_PER_CTA + wid;

    const float* __restrict__ c = coeff + (size_t)atom * NCOEF;

    // Lane i<21 loads coefficient i; broadcast via shfl
    float cval = (lane < NCOEF) ? __ldg(c + lane) : 0.0f;

    float p[12];
    #pragma unroll
    for (int i = 0; i < 12; i++)
        p[i] = __shfl_sync(0xffffffffu, cval, 9 + i);

    // Every lane redundantly computes norms + unit vectors
    float n[4], hx[4], hy[4], hz[4];
    #pragma unroll
    for (int q = 0; q < 4; q++) {
        float px = p[3*q], py = p[3*q+1], pz = p[3*q+2];
        float nn = sqrtf(px*px + py*py + pz*pz);
        n[q] = nn;
        bool zm = (fabsf(px) < 1e-12f) && (fabsf(py) < 1e-12f) && (fabsf(pz) < 1e-12f);
        float inv = zm ? 0.0f : (1.0f / nn);
        hx[q] = px * inv; hy[q] = py * inv; hz[q] = pz * inv;
    }

    // 6 pairs: cos, sin (angle in [0,pi] -> sin >= 0), average distance
    float pcos[6], psin[6], pavd[6];
    {
        const int iu[6] = {0, 0, 0, 1, 1, 2};
        const int ju[6] = {1, 2, 3, 2, 3, 3};
        #pragma unroll
        for (int e = 0; e < 6; e++) {
            int i = iu[e], j = ju[e];
            float cs = hx[i]*hx[j] + hy[i]*hy[j] + hz[i]*hz[j];
            cs = fminf(0.9999f, fmaxf(-0.9999f, cs));
            pcos[e] = cs;
            psin[e] = sqrtf(fmaxf(0.0f, 1.0f - cs*cs));
            pavd[e] = (n[i] + n[j]) * 0.5f;
        }
    }

    // Stage s_coeffs + norms for the exp region
    if (lane < 9)        s_sn[wid][lane] = cval;
    else if (lane < 13)  s_sn[wid][lane] = n[lane - 9];

    // ---- Table build: idx = lane + 32t; k = idx&15 = lane&15 (lane-invariant
    // across rounds!); p = idx>>4 = (lane>>4) + 2t (select between 2 regs).
    const int k = lane & 15;
    const bool hi = (lane & 16) != 0;
    float st, ct;
    sincospif((float)k * (1.0f / 15.0f), &st, &ct);    // theta_k = k*pi/15
    const float kstep = (float)k * STEP_A;

    float ft_reg[3];                                    // lane owns ft[lane+32t]
    #pragma unroll
    for (int t = 0; t < 3; t++) {
        float cs = hi ? pcos[2*t+1] : pcos[2*t];
        float sn = hi ? psin[2*t+1] : psin[2*t];
        float av = hi ? pavd[2*t+1] : pavd[2*t];
        float cosd = cs * ct + sn * st;                 // cos(angle - theta_k)
        float b  = 0.5f * (1.0f + cosd);
        float b2 = b*b, b4 = b2*b2;
        ft_reg[t] = b4 * b4 * 0.0078125f;               // 2^(1-8) * b^8
        float d = av - kstep;
        reinterpret_cast<float*>(s_fd[wid])[lane + 32*t] = __expf(-8.0f * d * d);
    }
    __syncwarp();

    // Pre-load this lane's 6 f_dist float4s (pair p, dist group lane&3)
    float4 fd_regs[6];
    #pragma unroll
    for (int pp = 0; pp < 6; pp++)
        fd_regs[pp] = s_fd[wid][pp*4 + (lane & 3)];

    float4* __restrict__ o4 =
        reinterpret_cast<float4*>(out + (size_t)atom * OUT_PER_ATOM);

    // ---- Angular: 12 rounds, register-fed. f = lane+32r:
    //   pair     = f>>6 = r>>1            (uniform per round)
    //   ft index = f>>2 = 8r + (lane>>2)  -> shfl from owning lane
    //   fd       = fd_regs[r>>1]          (this lane's dist group)
    #pragma unroll
    for (int r = 0; r < 12; r++) {
        float ft = __shfl_sync(0xffffffffu, ft_reg[r >> 2],
                               ((r & 3) << 3) + (lane >> 2));
        float4 fd = fd_regs[r >> 1];
        float4 v  = make_float4(ft*fd.x, ft*fd.y, ft*fd.z, ft*fd.w);
        o4[EXP_VEC4 + (lane + 32*r)] = v;     // default write-back policy
    }

    // ---- s + radial regions: 52 vec4 in 2 rounds
    #pragma unroll
    for (int r = 0; r < 2; r++) {
        int t = lane + 32*r;
        if (t < EXP_VEC4) {
            bool isS = t < 36;
            int  q   = isS ? (t >> 2) : (9 + ((t - 36) >> 2));
            float x    = s_sn[wid][q];
            float base = isS ? (-4.0f + (float)((t & 3) * 4) * STEP_S)
                             : ((float)((t & 3) * 4) * STEP_R);
            float step = isS ? STEP_S : STEP_R;
            float eta  = isS ? 16.0f : 8.0f;
            float d0 = x - base, d1 = d0 - step, d2 = d1 - step, d3 = d2 - step;
            float4 v = make_float4(__expf(-eta*d0*d0), __expf(-eta*d1*d1),
                                   __expf(-eta*d2*d2), __expf(-eta*d3*d3));
            o4[t] = v;                         // default write-back policy
        }
    }
}

extern "C" void kernel_launch(void* const* d_in, const int* in_sizes, int n_in,
                              void* d_out, int out_size)
{
    const float* coeff = (const float*)d_in[0];   // [1024, 64, 21] fp32
    float* out = (float*)d_out;                   // [1024, 64, 1744] fp32

    // one warp per atom: 65536 atoms / 8 warps per CTA
    aev_kernel<<<65536 / WARPS_PER_CTA, 32 * WARPS_PER_CTA>>>(coeff, out);
}

// round 15
// speedup vs baseline: 1.0957x; 1.0957x over previous
#include <cuda_runtime.h>
#include <math.h>

#define NCOEF 21
#define OUT_PER_ATOM 1744          // 144 s + 64 radial + 1536 angular
#define EXP_VEC4 52                // (144+64)/4
#define WARPS_PER_CTA 8
#define STEP_S (8.0f / 15.0f)
#define STEP_R (4.0f / 15.0f)
#define STEP_A (4.0f / 15.0f)

__global__ __launch_bounds__(256, 5) void aev_kernel(const float* __restrict__ coeff,
                                                     float* __restrict__ out)
{
    // Per-warp private smem (only __syncwarp needed)
    __shared__ float4 s_fd[WARPS_PER_CTA][24];   // f_dist  [pair*4 + j4]
    __shared__ float  s_sn[WARPS_PER_CTA][16];   // [0..8]=s_coeffs, [9..12]=norms

    const int lane = threadIdx.x & 31;
    const int wid  = threadIdx.x >> 5;
    const int atom = blockIdx.x * WARPS_PER_CTA + wid;

    const float* __restrict__ c = coeff + (size_t)atom * NCOEF;

    // Lane i<21 loads coefficient i; broadcast via shfl
    float cval = (lane < NCOEF) ? __ldg(c + lane) : 0.0f;

    float p[12];
    #pragma unroll
    for (int i = 0; i < 12; i++)
        p[i] = __shfl_sync(0xffffffffu, cval, 9 + i);

    // Every lane redundantly computes norms + unit vectors
    float n[4], hx[4], hy[4], hz[4];
    #pragma unroll
    for (int q = 0; q < 4; q++) {
        float px = p[3*q], py = p[3*q+1], pz = p[3*q+2];
        float nn = sqrtf(px*px + py*py + pz*pz);
        n[q] = nn;
        bool zm = (fabsf(px) < 1e-12f) && (fabsf(py) < 1e-12f) && (fabsf(pz) < 1e-12f);
        float inv = zm ? 0.0f : (1.0f / nn);
        hx[q] = px * inv; hy[q] = py * inv; hz[q] = pz * inv;
    }

    // 6 pairs: cos, sin (angle in [0,pi] -> sin >= 0), average distance
    float pcos[6], psin[6], pavd[6];
    {
        const int iu[6] = {0, 0, 0, 1, 1, 2};
        const int ju[6] = {1, 2, 3, 2, 3, 3};
        #pragma unroll
        for (int e = 0; e < 6; e++) {
            int i = iu[e], j = ju[e];
            float cs = hx[i]*hx[j] + hy[i]*hy[j] + hz[i]*hz[j];
            cs = fminf(0.9999f, fmaxf(-0.9999f, cs));
            pcos[e] = cs;
            psin[e] = sqrtf(fmaxf(0.0f, 1.0f - cs*cs));
            pavd[e] = (n[i] + n[j]) * 0.5f;
        }
    }

    // Stage s_coeffs + norms for the exp region
    if (lane < 9)        s_sn[wid][lane] = cval;
    else if (lane < 13)  s_sn[wid][lane] = n[lane - 9];

    // ---- Table build: idx = lane + 32t; k = idx&15 = lane&15 (lane-invariant
    // across rounds!); p = idx>>4 = (lane>>4) + 2t (select between 2 regs).
    const int k = lane & 15;
    const bool hi = (lane & 16) != 0;
    float st, ct;
    sincospif((float)k * (1.0f / 15.0f), &st, &ct);    // theta_k = k*pi/15
    const float kstep = (float)k * STEP_A;

    float ft_reg[3];                                    // lane owns ft[lane+32t]
    #pragma unroll
    for (int t = 0; t < 3; t++) {
        float cs = hi ? pcos[2*t+1] : pcos[2*t];
        float sn = hi ? psin[2*t+1] : psin[2*t];
        float av = hi ? pavd[2*t+1] : pavd[2*t];
        float cosd = cs * ct + sn * st;                 // cos(angle - theta_k)
        float b  = 0.5f * (1.0f + cosd);
        float b2 = b*b, b4 = b2*b2;
        ft_reg[t] = b4 * b4 * 0.0078125f;               // 2^(1-8) * b^8
        float d = av - kstep;
        reinterpret_cast<float*>(s_fd[wid])[lane + 32*t] = __expf(-8.0f * d * d);
    }
    __syncwarp();

    // Pre-load this lane's 6 f_dist float4s (pair p, dist group lane&3)
    float4 fd_regs[6];
    #pragma unroll
    for (int pp = 0; pp < 6; pp++)
        fd_regs[pp] = s_fd[wid][pp*4 + (lane & 3)];

    float4* __restrict__ o4 =
        reinterpret_cast<float4*>(out + (size_t)atom * OUT_PER_ATOM);

    // ---- Angular: 12 rounds, register-fed. f = lane+32r:
    //   pair     = f>>6 = r>>1            (uniform per round)
    //   ft index = f>>2 = 8r + (lane>>2)  -> shfl from owning lane
    //   fd       = fd_regs[r>>1]          (this lane's dist group)
    #pragma unroll
    for (int r = 0; r < 12; r++) {
        float ft = __shfl_sync(0xffffffffu, ft_reg[r >> 2],
                               ((r & 3) << 3) + (lane >> 2));
        float4 fd = fd_regs[r >> 1];
        float4 v  = make_float4(ft*fd.x, ft*fd.y, ft*fd.z, ft*fd.w);
        __stcs(&o4[EXP_VEC4 + (lane + 32*r)], v);
    }

    // ---- s + radial regions: 52 vec4 in 2 rounds
    #pragma unroll
    for (int r = 0; r < 2; r++) {
        int t = lane + 32*r;
        if (t < EXP_VEC4) {
            bool isS = t < 36;
            int  q   = isS ? (t >> 2) : (9 + ((t - 36) >> 2));
            float x    = s_sn[wid][q];
            float base = isS ? (-4.0f + (float)((t & 3) * 4) * STEP_S)
                             : ((float)((t & 3) * 4) * STEP_R);
            float step = isS ? STEP_S : STEP_R;
            float eta  = isS ? 16.0f : 8.0f;
            float d0 = x - base, d1 = d0 - step, d2 = d1 - step, d3 = d2 - step;
            float4 v = make_float4(__expf(-eta*d0*d0), __expf(-eta*d1*d1),
                                   __expf(-eta*d2*d2), __expf(-eta*d3*d3));
            __stcs(&o4[t], v);
        }
    }
}

extern "C" void kernel_launch(void* const* d_in, const int* in_sizes, int n_in,
                              void* d_out, int out_size)
{
    const float* coeff = (const float*)d_in[0];   // [1024, 64, 21] fp32
    float* out = (float*)d_out;                   // [1024, 64, 1744] fp32

    // one warp per atom: 65536 atoms / 8 warps per CTA
    aev_kernel<<<65536 / WARPS_PER_CTA, 32 * WARPS_PER_CTA>>>(coeff, out);
}